// round 6
// baseline (speedup 1.0000x reference)
#include <cuda_runtime.h>

// Shapes (fixed for this problem)
#define IN_F   2048
#define OUT_F  8192
#define NROWS  8192
#define NBLK   4096   // 64 in-blocks (32 cols) x 64 out-blocks (128 rows)
#define TOPK   410    // ceil(4096 * 0.1)

// Scratch (no device allocation allowed)
__device__ float g_scores[NBLK];
__device__ int   g_klist[64 * 64];   // per out-group list of selected in-block indices
__device__ int   g_kcount[64];

// ---------------------------------------------------------------------------
// Kernel 1: per-block sum of |W|. Block b = i*64 + j, i = in-block (32 cols),
// j = out-block (128 rows). Matches pooled.reshape(-1) flat index (i major).
// ---------------------------------------------------------------------------
__global__ void block_score_kernel(const float* __restrict__ W) {
    const int b = blockIdx.x;
    const int i = b >> 6;
    const int j = b & 63;
    const int t = threadIdx.x;  // 128 threads: one out-row each
    const float4* row =
        reinterpret_cast<const float4*>(W + (size_t)(j * 128 + t) * IN_F + i * 32);
    float s = 0.f;
#pragma unroll
    for (int c = 0; c < 8; ++c) {
        float4 v = row[c];
        s += fabsf(v.x) + fabsf(v.y) + fabsf(v.z) + fabsf(v.w);
    }
    __shared__ float red[128];
    red[t] = s;
    __syncthreads();
    for (int off = 64; off > 0; off >>= 1) {
        if (t < off) red[t] += red[t + off];
        __syncthreads();
    }
    if (t == 0) g_scores[b] = red[0];
}

// ---------------------------------------------------------------------------
// Kernel 2: single-CTA bitonic sort (desc, idx-asc tiebreak), mark top-410,
// build per-out-group compacted K-block lists.
// ---------------------------------------------------------------------------
__global__ void topk_kernel() {
    __shared__ float         val[NBLK];
    __shared__ int           idx[NBLK];
    __shared__ unsigned char sel[NBLK];
    const int t = threadIdx.x;  // 1024
    for (int p = t; p < NBLK; p += 1024) {
        val[p] = g_scores[p];
        idx[p] = p;
        sel[p] = 0;
    }
    __syncthreads();
    for (int k = 2; k <= NBLK; k <<= 1) {
        for (int j = k >> 1; j > 0; j >>= 1) {
            for (int p = t; p < NBLK; p += 1024) {
                int l = p ^ j;
                if (l > p) {
                    float v0 = val[p], v1 = val[l];
                    int   i0 = idx[p], i1 = idx[l];
                    // "p greater than l" with jax-style tiebreak (lower index wins)
                    bool g01  = (v0 > v1) || (v0 == v1 && i0 < i1);
                    bool desc = ((p & k) == 0);
                    if (desc ? !g01 : g01) {
                        val[p] = v1; val[l] = v0;
                        idx[p] = i1; idx[l] = i0;
                    }
                }
            }
            __syncthreads();
        }
    }
    for (int r = t; r < TOPK; r += 1024) sel[idx[r]] = 1;
    __syncthreads();
    if (t < 64) {  // t = out-group j
        int c = 0;
        for (int i = 0; i < 64; ++i)
            if (sel[i * 64 + t]) g_klist[t * 64 + (c++)] = i;
        g_kcount[t] = c;
    }
}

// ---------------------------------------------------------------------------
// Kernel 3: block-sparse SGEMM with packed f32x2 FMA.
//   C[m, n] = sum over selected K-blocks of x[m, k] * W[n, k]  + b[n]
// Tiles: BM = BN = 128, BK = 32. 256 threads, 8x8 per thread (4+4 split).
// SMEM stored transposed [k][128] with a k-dependent rotation swizzle:
//   phys(k, m) = (m & ~31) | ((m + 4*((k>>2 + 4*(m>>5)) & 7)) & 31)
// -> conflict-free transpose stores; 2-phase LDS.128 reads.
// ---------------------------------------------------------------------------
__device__ __forceinline__ unsigned long long pack_dup(float x) {
    unsigned long long r;
    unsigned u = __float_as_uint(x);
    asm("mov.b64 %0, {%1, %1};" : "=l"(r) : "r"(u));
    return r;
}
__device__ __forceinline__ unsigned long long pack2(float x, float y) {
    unsigned long long r;
    asm("mov.b64 %0, {%1, %2};" : "=l"(r) : "r"(__float_as_uint(x)), "r"(__float_as_uint(y)));
    return r;
}
#define FMA2(d, a, b) asm("fma.rn.f32x2 %0, %1, %2, %0;" : "+l"(d) : "l"(a), "l"(b))

__global__ __launch_bounds__(256, 2)
void sparse_gemm_kernel(const float* __restrict__ X, const float* __restrict__ W,
                        const float* __restrict__ B, float* __restrict__ out) {
    __shared__ float As[32][128];
    __shared__ float Bs[32][128];

    const int ng = blockIdx.x;          // out-group (n), 0..63
    const int mt = blockIdx.y;          // m tile, 0..63
    const int n0 = ng << 7;
    const int m0 = mt << 7;

    const int tid = threadIdx.x;
    const int tx  = tid & 15;
    const int ty  = tid >> 4;
    const int cst = tid & 7;            // k-quad for loads (k = 4*cst + q)
    const int mst = tid >> 3;           // row-in-32 for loads

    unsigned long long acc[8][4];
#pragma unroll
    for (int i = 0; i < 8; ++i)
#pragma unroll
        for (int j = 0; j < 4; ++j) acc[i][j] = 0ULL;

    const int cnt = g_kcount[ng];

    for (int it = 0; it < cnt; ++it) {
        const int k0 = g_klist[(ng << 6) + it] << 5;

        // Load 128x32 tiles of X and W, transpose into SMEM with swizzle.
#pragma unroll
        for (int r = 0; r < 4; ++r) {
            const int m = (r << 5) + mst;
            float4 a = *reinterpret_cast<const float4*>(
                X + (size_t)(m0 + m) * IN_F + k0 + (cst << 2));
            float4 w = *reinterpret_cast<const float4*>(
                W + (size_t)(n0 + m) * IN_F + k0 + (cst << 2));
            const int rot = ((cst + (r << 2)) & 7) << 2;
            const int p   = (r << 5) | ((mst + rot) & 31);
            const int kb  = cst << 2;
            As[kb + 0][p] = a.x; As[kb + 1][p] = a.y;
            As[kb + 2][p] = a.z; As[kb + 3][p] = a.w;
            Bs[kb + 0][p] = w.x; Bs[kb + 1][p] = w.y;
            Bs[kb + 2][p] = w.z; Bs[kb + 3][p] = w.w;
        }
        __syncthreads();

#pragma unroll 8
        for (int k = 0; k < 32; ++k) {
            const int c  = k >> 2;
            const int rE = c << 2;                    // rotation, even 32-groups
            const int rO = ((c + 4) & 7) << 2;        // rotation, odd 32-groups
            // A fragment rows: ty*4 + {0..3} and 64 + ty*4 + {0..3}
            const int pA = ((ty & 8) << 2) | ((((ty & 7) << 2) + ((ty & 8) ? rO : rE)) & 31);
            // B fragment cols: tx*4 + {0..3} and 64 + tx*4 + {0..3}
            const int pB = ((tx & 8) << 2) | ((((tx & 7) << 2) + ((tx & 8) ? rO : rE)) & 31);

            float4 a0 = *reinterpret_cast<const float4*>(&As[k][pA]);
            float4 a1 = *reinterpret_cast<const float4*>(&As[k][pA + 64]);
            float4 b0 = *reinterpret_cast<const float4*>(&Bs[k][pB]);
            float4 b1 = *reinterpret_cast<const float4*>(&Bs[k][pB + 64]);

            unsigned long long Bp0 = pack2(b0.x, b0.y);
            unsigned long long Bp1 = pack2(b0.z, b0.w);
            unsigned long long Bp2 = pack2(b1.x, b1.y);
            unsigned long long Bp3 = pack2(b1.z, b1.w);

            const float av[8] = {a0.x, a0.y, a0.z, a0.w, a1.x, a1.y, a1.z, a1.w};
#pragma unroll
            for (int ii = 0; ii < 8; ++ii) {
                unsigned long long aa = pack_dup(av[ii]);
                FMA2(acc[ii][0], aa, Bp0);
                FMA2(acc[ii][1], aa, Bp1);
                FMA2(acc[ii][2], aa, Bp2);
                FMA2(acc[ii][3], aa, Bp3);
            }
        }
        __syncthreads();
    }

    // Epilogue: unpack, add bias, store.
    float bl[8];
#pragma unroll
    for (int j = 0; j < 4; ++j) bl[j] = B[n0 + (tx << 2) + j];
#pragma unroll
    for (int j = 0; j < 4; ++j) bl[4 + j] = B[n0 + 64 + (tx << 2) + j];

#pragma unroll
    for (int ii = 0; ii < 8; ++ii) {
        const int lm = (ii < 4) ? ((ty << 2) + ii) : (64 + (ty << 2) + ii - 4);
        float f[8];
#pragma unroll
        for (int jb = 0; jb < 4; ++jb) {
            unsigned lo, hi;
            asm("mov.b64 {%0, %1}, %2;" : "=r"(lo), "=r"(hi) : "l"(acc[ii][jb]));
            f[2 * jb]     = __uint_as_float(lo);
            f[2 * jb + 1] = __uint_as_float(hi);
        }
        float* orow = out + (size_t)(m0 + lm) * OUT_F + n0;
        float4 o0 = make_float4(f[0] + bl[0], f[1] + bl[1], f[2] + bl[2], f[3] + bl[3]);
        float4 o1 = make_float4(f[4] + bl[4], f[5] + bl[5], f[6] + bl[6], f[7] + bl[7]);
        *reinterpret_cast<float4*>(orow + (tx << 2))      = o0;
        *reinterpret_cast<float4*>(orow + 64 + (tx << 2)) = o1;
    }
}

// ---------------------------------------------------------------------------
extern "C" void kernel_launch(void* const* d_in, const int* in_sizes, int n_in,
                              void* d_out, int out_size) {
    (void)in_sizes; (void)n_in; (void)out_size;
    const float* X = (const float*)d_in[0];   // (8192, 2048)
    const float* W = (const float*)d_in[1];   // (8192, 2048)
    const float* B = (const float*)d_in[2];   // (8192,)
    float* out = (float*)d_out;               // (8192, 8192)

    block_score_kernel<<<NBLK, 128>>>(W);
    topk_kernel<<<1, 1024>>>();
    sparse_gemm_kernel<<<dim3(64, 64), 256>>>(X, W, B, out);
}

// round 8
// speedup vs baseline: 1.6318x; 1.6318x over previous
#include <cuda_runtime.h>
#include <cstdint>

#define IN_F   2048
#define OUT_F  8192
#define NROWS  8192
#define NBLK   4096   // 64 in-blocks (32 cols) x 64 out-blocks (128 rows)
#define TOPK   410

// ---------------------------------------------------------------------------
// Scratch (static device memory; no runtime allocation)
// ---------------------------------------------------------------------------
__device__ float g_scores[NBLK];
__device__ int   g_klist[64 * 64];
__device__ int   g_kcount[64];
// Packed bf16 hi|lo: row = 64 blocks x (32 hi + 32 lo) = 4096 ushorts (8192 B)
__device__ __align__(16) unsigned short g_Xc[(size_t)NROWS * 4096];
__device__ __align__(16) unsigned short g_Wc[(size_t)OUT_F * 4096];

// ---------------------------------------------------------------------------
// Helpers
// ---------------------------------------------------------------------------
__device__ __forceinline__ uint32_t smem_u32(const void* p) {
    uint32_t r;
    asm("{ .reg .u64 t; cvta.to.shared.u64 t, %1; cvt.u32.u64 %0, t; }"
        : "=r"(r) : "l"(p));
    return r;
}
#define SWZ(o) ((o) ^ (((o) >> 3) & 0x70))

__device__ __forceinline__ void cp_async16(uint32_t dst, const void* src) {
    asm volatile("cp.async.cg.shared.global [%0], [%1], 16;" :: "r"(dst), "l"(src));
}

__device__ __forceinline__ void ldsm_x4(uint32_t* r, uint32_t addr) {
    asm volatile("ldmatrix.sync.aligned.m8n8.x4.shared.b16 {%0,%1,%2,%3}, [%4];"
                 : "=r"(r[0]), "=r"(r[1]), "=r"(r[2]), "=r"(r[3]) : "r"(addr));
}
__device__ __forceinline__ void ldsm_x2(uint32_t* r, uint32_t addr) {
    asm volatile("ldmatrix.sync.aligned.m8n8.x2.shared.b16 {%0,%1}, [%2];"
                 : "=r"(r[0]), "=r"(r[1]) : "r"(addr));
}
__device__ __forceinline__ void mma16816(float* d, const uint32_t* a, const uint32_t* b) {
    asm volatile(
        "mma.sync.aligned.m16n8k16.row.col.f32.bf16.bf16.f32 "
        "{%0,%1,%2,%3}, {%4,%5,%6,%7}, {%8,%9}, {%0,%1,%2,%3};"
        : "+f"(d[0]), "+f"(d[1]), "+f"(d[2]), "+f"(d[3])
        : "r"(a[0]), "r"(a[1]), "r"(a[2]), "r"(a[3]), "r"(b[0]), "r"(b[1]));
}

// ---------------------------------------------------------------------------
// Kernel A: fp32 -> packed bf16 hi|lo, block-interleaved layout.
// Row layout (uint4 units, 512/row): block kb at kb*8; hi chunks +0..3, lo +4..7
// ---------------------------------------------------------------------------
__global__ __launch_bounds__(256)
void convert_hilo(const float* __restrict__ src, int which) {
    unsigned short* dst = which ? g_Wc : g_Xc;
    size_t t = (size_t)blockIdx.x * 256 + threadIdx.x;
    int    k8 = (int)(t & 255);
    size_t m  = t >> 8;
    int kb = k8 >> 2, jc = k8 & 3;

    const float4* s4 = reinterpret_cast<const float4*>(src) + t * 2;
    float4 a = s4[0], b = s4[1];

    uint4 hi;
    hi.x = __byte_perm(__float_as_uint(a.x), __float_as_uint(a.y), 0x7632);
    hi.y = __byte_perm(__float_as_uint(a.z), __float_as_uint(a.w), 0x7632);
    hi.z = __byte_perm(__float_as_uint(b.x), __float_as_uint(b.y), 0x7632);
    hi.w = __byte_perm(__float_as_uint(b.z), __float_as_uint(b.w), 0x7632);

    float l0 = a.x - __uint_as_float(__float_as_uint(a.x) & 0xFFFF0000u);
    float l1 = a.y - __uint_as_float(__float_as_uint(a.y) & 0xFFFF0000u);
    float l2 = a.z - __uint_as_float(__float_as_uint(a.z) & 0xFFFF0000u);
    float l3 = a.w - __uint_as_float(__float_as_uint(a.w) & 0xFFFF0000u);
    float l4 = b.x - __uint_as_float(__float_as_uint(b.x) & 0xFFFF0000u);
    float l5 = b.y - __uint_as_float(__float_as_uint(b.y) & 0xFFFF0000u);
    float l6 = b.z - __uint_as_float(__float_as_uint(b.z) & 0xFFFF0000u);
    float l7 = b.w - __uint_as_float(__float_as_uint(b.w) & 0xFFFF0000u);

    uint4 lo;
    asm("cvt.rn.bf16x2.f32 %0, %1, %2;" : "=r"(lo.x) : "f"(l1), "f"(l0));
    asm("cvt.rn.bf16x2.f32 %0, %1, %2;" : "=r"(lo.y) : "f"(l3), "f"(l2));
    asm("cvt.rn.bf16x2.f32 %0, %1, %2;" : "=r"(lo.z) : "f"(l5), "f"(l4));
    asm("cvt.rn.bf16x2.f32 %0, %1, %2;" : "=r"(lo.w) : "f"(l7), "f"(l6));

    uint4* d4 = reinterpret_cast<uint4*>(dst);
    size_t base = m * 512 + (size_t)kb * 8 + jc;
    d4[base]     = hi;
    d4[base + 4] = lo;
}

// ---------------------------------------------------------------------------
// Kernel B: per-block sum of |W|
// ---------------------------------------------------------------------------
__global__ void block_score_kernel(const float* __restrict__ W) {
    const int b = blockIdx.x;
    const int i = b >> 6;
    const int j = b & 63;
    const int t = threadIdx.x;
    const float4* row =
        reinterpret_cast<const float4*>(W + (size_t)(j * 128 + t) * IN_F + i * 32);
    float s = 0.f;
#pragma unroll
    for (int c = 0; c < 8; ++c) {
        float4 v = row[c];
        s += fabsf(v.x) + fabsf(v.y) + fabsf(v.z) + fabsf(v.w);
    }
    __shared__ float red[128];
    red[t] = s;
    __syncthreads();
    for (int off = 64; off > 0; off >>= 1) {
        if (t < off) red[t] += red[t + off];
        __syncthreads();
    }
    if (t == 0) g_scores[b] = red[0];
}

// ---------------------------------------------------------------------------
// Kernel C: bitonic sort top-k + per-out-group K-block lists
// ---------------------------------------------------------------------------
__global__ void topk_kernel() {
    __shared__ float         val[NBLK];
    __shared__ int           idx[NBLK];
    __shared__ unsigned char sel[NBLK];
    const int t = threadIdx.x;
    for (int p = t; p < NBLK; p += 1024) {
        val[p] = g_scores[p];
        idx[p] = p;
        sel[p] = 0;
    }
    __syncthreads();
    for (int k = 2; k <= NBLK; k <<= 1) {
        for (int j = k >> 1; j > 0; j >>= 1) {
            for (int p = t; p < NBLK; p += 1024) {
                int l = p ^ j;
                if (l > p) {
                    float v0 = val[p], v1 = val[l];
                    int   i0 = idx[p], i1 = idx[l];
                    bool g01  = (v0 > v1) || (v0 == v1 && i0 < i1);
                    bool desc = ((p & k) == 0);
                    if (desc ? !g01 : g01) {
                        val[p] = v1; val[l] = v0;
                        idx[p] = i1; idx[l] = i0;
                    }
                }
            }
            __syncthreads();
        }
    }
    for (int r = t; r < TOPK; r += 1024) sel[idx[r]] = 1;
    __syncthreads();
    if (t < 64) {
        int c = 0;
        for (int i = 0; i < 64; ++i)
            if (sel[i * 64 + t]) g_klist[t * 64 + (c++)] = i;
        g_kcount[t] = c;
    }
}

// ---------------------------------------------------------------------------
// Kernel D: block-sparse GEMM on mma.sync (bf16 hi/lo split, fp32 accum)
// CTA tile 128x128, BK=32 per selected block; 8 warps, warp tile 64x32.
// SMEM per stage: As (X, 128 rows x 128B) + Bs (W, same) = 32 KB, 2 stages.
// Row layout: bytes [0,64) = hi bf16 x32, [64,128) = lo bf16 x32, swizzled:
//   phys(row, b) = row*128 + (b ^ ((row&7)<<4))
// ---------------------------------------------------------------------------
#define AS_OFF      0
#define BS_OFF      16384
#define STAGE_BYTES 32768
#define SMEM_TOTAL  65536

__device__ __forceinline__ void load_tiles(uint32_t stage_base,
                                           const uint4* __restrict__ XC,
                                           const uint4* __restrict__ WC,
                                           int m0, int n0, int kb, int tid) {
    const size_t kb8 = (size_t)kb * 8;
#pragma unroll
    for (int j = 0; j < 4; ++j) {
        int q   = tid + (j << 8);           // 0..1023
        int row = q >> 3;
        int c   = q & 7;
        uint32_t sw = SWZ((uint32_t)(q << 4));
        cp_async16(stage_base + AS_OFF + sw, XC + (size_t)(m0 + row) * 512 + kb8 + c);
        cp_async16(stage_base + BS_OFF + sw, WC + (size_t)(n0 + row) * 512 + kb8 + c);
    }
}

__global__ __launch_bounds__(256)
void mma_kernel(const float* __restrict__ Bias, float* __restrict__ out) {
    extern __shared__ char smem[];
    const uint32_t sb  = smem_u32(smem);
    const int tid  = threadIdx.x;
    const int wid  = tid >> 5;
    const int lane = tid & 31;
    const int ng   = blockIdx.x;
    const int mt   = blockIdx.y;
    const int n0   = ng << 7;
    const int m0   = mt << 7;
    const int cnt  = g_kcount[ng];

    const int wm = wid & 1;        // m half: 0/1 (64 rows each)
    const int wn = wid >> 1;       // n strip: 0..3 (32 cols each)

    if (cnt == 0) {
        // bias-only tile
        const int r  = tid >> 1;
        const int ch = (tid & 1) << 6;
        const float4* bsrc = reinterpret_cast<const float4*>(Bias + n0 + ch);
        float4* drow = reinterpret_cast<float4*>(out + (size_t)(m0 + r) * OUT_F + n0 + ch);
#pragma unroll
        for (int c = 0; c < 16; ++c) drow[c] = bsrc[c];
        return;
    }

    float acc[4][4][4];
#pragma unroll
    for (int i = 0; i < 4; ++i)
#pragma unroll
        for (int j = 0; j < 4; ++j)
#pragma unroll
            for (int k = 0; k < 4; ++k) acc[i][j][k] = 0.f;

    // per-lane ldmatrix addressing components
    const int rowA   = (wm << 6) + (lane & 15);           // within 128-row tile
    const uint32_t aRowOff = (uint32_t)rowA << 7;
    const uint32_t aRot    = (uint32_t)(rowA & 7) << 4;
    const uint32_t aLaneB  = (lane & 16) ? 16u : 0u;

    const int rowB   = (wn << 5) + (lane & 7);
    const uint32_t bRowOff = (uint32_t)rowB << 7;
    const uint32_t bRot    = (uint32_t)(lane & 7) << 4;
    const uint32_t bLaneB  = (lane & 8) ? 16u : 0u;

    const uint4* XC = reinterpret_cast<const uint4*>(g_Xc);
    const uint4* WC = reinterpret_cast<const uint4*>(g_Wc);
    const int* klist = g_klist + (ng << 6);

    // prologue
    load_tiles(sb, XC, WC, m0, n0, klist[0], tid);
    asm volatile("cp.async.commit_group;");

    for (int it = 0; it < cnt; ++it) {
        const int s = it & 1;
        if (it + 1 < cnt) {
            load_tiles(sb + (s ^ 1) * STAGE_BYTES, XC, WC, m0, n0, klist[it + 1], tid);
            asm volatile("cp.async.commit_group;");
            asm volatile("cp.async.wait_group 1;");
        } else {
            asm volatile("cp.async.wait_group 0;");
        }
        __syncthreads();

        const uint32_t aBase = sb + s * STAGE_BYTES + AS_OFF;
        const uint32_t bBase = sb + s * STAGE_BYTES + BS_OFF;

#pragma unroll
        for (int p = 0; p < 3; ++p) {
            const uint32_t aOff = (p == 2) ? 64u : 0u;   // (hi,hi),(hi,lo),(lo,hi)
            const uint32_t bOff = (p == 1) ? 64u : 0u;
#pragma unroll
            for (int s16 = 0; s16 < 2; ++s16) {
                const uint32_t bA = aOff + (uint32_t)(s16 << 5) + aLaneB;
                const uint32_t bB = bOff + (uint32_t)(s16 << 5) + bLaneB;

                uint32_t afr[4][4];
#pragma unroll
                for (int i = 0; i < 4; ++i)
                    ldsm_x4(afr[i], aBase + (i << 11) + aRowOff + (bA ^ aRot));

                uint32_t bfr[4][2];
#pragma unroll
                for (int j = 0; j < 4; ++j)
                    ldsm_x2(bfr[j], bBase + (j << 10) + bRowOff + (bB ^ bRot));

#pragma unroll
                for (int i = 0; i < 4; ++i)
#pragma unroll
                    for (int j = 0; j < 4; ++j)
                        mma16816(acc[i][j], afr[i], bfr[j]);
            }
        }
        __syncthreads();
    }

    // Epilogue: d0,d1 -> (row lane>>2, cols 2*(lane&3)), d2,d3 -> row+8
    const int cLane = (lane & 3) << 1;
    const int rLane = lane >> 2;
#pragma unroll
    for (int j = 0; j < 4; ++j) {
        const int col = n0 + (wn << 5) + (j << 3) + cLane;
        const float2 bv = *reinterpret_cast<const float2*>(Bias + col);
#pragma unroll
        for (int i = 0; i < 4; ++i) {
            const int row = m0 + (wm << 6) + (i << 4) + rLane;
            float2 o0 = make_float2(acc[i][j][0] + bv.x, acc[i][j][1] + bv.y);
            float2 o1 = make_float2(acc[i][j][2] + bv.x, acc[i][j][3] + bv.y);
            *reinterpret_cast<float2*>(out + (size_t)row * OUT_F + col)       = o0;
            *reinterpret_cast<float2*>(out + (size_t)(row + 8) * OUT_F + col) = o1;
        }
    }
}

// ---------------------------------------------------------------------------
extern "C" void kernel_launch(void* const* d_in, const int* in_sizes, int n_in,
                              void* d_out, int out_size) {
    (void)in_sizes; (void)n_in; (void)out_size;
    const float* X = (const float*)d_in[0];   // (8192, 2048)
    const float* W = (const float*)d_in[1];   // (8192, 2048)
    const float* B = (const float*)d_in[2];   // (8192,)
    float* out = (float*)d_out;               // (8192, 8192)

    cudaFuncSetAttribute(mma_kernel, cudaFuncAttributeMaxDynamicSharedMemorySize,
                         SMEM_TOTAL);

    convert_hilo<<<8192, 256>>>(X, 0);
    convert_hilo<<<8192, 256>>>(W, 1);
    block_score_kernel<<<NBLK, 128>>>(W);
    topk_kernel<<<1, 1024>>>();
    mma_kernel<<<dim3(64, 64), 256, SMEM_TOTAL>>>(B, out);
}

// round 9
// speedup vs baseline: 2.1741x; 1.3323x over previous
#include <cuda_runtime.h>
#include <cstdint>

#define IN_F   2048
#define OUT_F  8192
#define NROWS  8192
#define NBLK   4096   // 64 in-blocks (32 cols) x 64 out-blocks (128 rows)
#define TOPK   410

// ---------------------------------------------------------------------------
// Scratch (static device memory; no runtime allocation)
// ---------------------------------------------------------------------------
__device__ float g_scores[NBLK];
__device__ int   g_klist[64 * 64];
__device__ int   g_kcount[64];
// Packed bf16 hi|lo: row = 64 blocks x (32 hi + 32 lo) = 4096 ushorts (8192 B)
__device__ __align__(16) unsigned short g_Xc[(size_t)NROWS * 4096];
__device__ __align__(16) unsigned short g_Wc[(size_t)OUT_F * 4096];

// ---------------------------------------------------------------------------
// Helpers
// ---------------------------------------------------------------------------
__device__ __forceinline__ uint32_t smem_u32(const void* p) {
    uint32_t r;
    asm("{ .reg .u64 t; cvta.to.shared.u64 t, %1; cvt.u32.u64 %0, t; }"
        : "=r"(r) : "l"(p));
    return r;
}
#define SWZ(o) ((o) ^ (((o) >> 3) & 0x70))

__device__ __forceinline__ void cp_async16(uint32_t dst, const void* src) {
    asm volatile("cp.async.cg.shared.global [%0], [%1], 16;" :: "r"(dst), "l"(src));
}

__device__ __forceinline__ void ldsm_x4(uint32_t* r, uint32_t addr) {
    asm volatile("ldmatrix.sync.aligned.m8n8.x4.shared.b16 {%0,%1,%2,%3}, [%4];"
                 : "=r"(r[0]), "=r"(r[1]), "=r"(r[2]), "=r"(r[3]) : "r"(addr));
}
__device__ __forceinline__ void ldsm_x2(uint32_t* r, uint32_t addr) {
    asm volatile("ldmatrix.sync.aligned.m8n8.x2.shared.b16 {%0,%1}, [%2];"
                 : "=r"(r[0]), "=r"(r[1]) : "r"(addr));
}
__device__ __forceinline__ void mma16816(float* d, const uint32_t* a, const uint32_t* b) {
    asm volatile(
        "mma.sync.aligned.m16n8k16.row.col.f32.bf16.bf16.f32 "
        "{%0,%1,%2,%3}, {%4,%5,%6,%7}, {%8,%9}, {%0,%1,%2,%3};"
        : "+f"(d[0]), "+f"(d[1]), "+f"(d[2]), "+f"(d[3])
        : "r"(a[0]), "r"(a[1]), "r"(a[2]), "r"(a[3]), "r"(b[0]), "r"(b[1]));
}

// ---------------------------------------------------------------------------
// Kernel A: fp32 -> packed bf16 hi|lo, block-interleaved layout.
// One CTA (256 threads) per row. For W (which=1): fused per-block |.| scoring.
// For X (which=0): block 0 also zeroes g_scores for this run.
// ---------------------------------------------------------------------------
__global__ __launch_bounds__(256)
void convert_hilo(const float* __restrict__ src, int which) {
    unsigned short* dst = which ? g_Wc : g_Xc;
    const int tid = threadIdx.x;
    const size_t m = blockIdx.x;           // row
    const int kb = tid >> 2, jc = tid & 3; // k-block, chunk within block

    if (!which && blockIdx.x == 0) {
#pragma unroll
        for (int p = tid; p < NBLK; p += 256) g_scores[p] = 0.f;
    }

    const float4* s4 = reinterpret_cast<const float4*>(src) + (m * 256 + tid) * 2;
    float4 a = s4[0], b = s4[1];

    uint4 hi;
    hi.x = __byte_perm(__float_as_uint(a.x), __float_as_uint(a.y), 0x7632);
    hi.y = __byte_perm(__float_as_uint(a.z), __float_as_uint(a.w), 0x7632);
    hi.z = __byte_perm(__float_as_uint(b.x), __float_as_uint(b.y), 0x7632);
    hi.w = __byte_perm(__float_as_uint(b.z), __float_as_uint(b.w), 0x7632);

    float l0 = a.x - __uint_as_float(__float_as_uint(a.x) & 0xFFFF0000u);
    float l1 = a.y - __uint_as_float(__float_as_uint(a.y) & 0xFFFF0000u);
    float l2 = a.z - __uint_as_float(__float_as_uint(a.z) & 0xFFFF0000u);
    float l3 = a.w - __uint_as_float(__float_as_uint(a.w) & 0xFFFF0000u);
    float l4 = b.x - __uint_as_float(__float_as_uint(b.x) & 0xFFFF0000u);
    float l5 = b.y - __uint_as_float(__float_as_uint(b.y) & 0xFFFF0000u);
    float l6 = b.z - __uint_as_float(__float_as_uint(b.z) & 0xFFFF0000u);
    float l7 = b.w - __uint_as_float(__float_as_uint(b.w) & 0xFFFF0000u);

    uint4 lo;
    asm("cvt.rn.bf16x2.f32 %0, %1, %2;" : "=r"(lo.x) : "f"(l1), "f"(l0));
    asm("cvt.rn.bf16x2.f32 %0, %1, %2;" : "=r"(lo.y) : "f"(l3), "f"(l2));
    asm("cvt.rn.bf16x2.f32 %0, %1, %2;" : "=r"(lo.z) : "f"(l5), "f"(l4));
    asm("cvt.rn.bf16x2.f32 %0, %1, %2;" : "=r"(lo.w) : "f"(l7), "f"(l6));

    uint4* d4 = reinterpret_cast<uint4*>(dst);
    size_t base = m * 512 + (size_t)kb * 8 + jc;
    d4[base]     = hi;
    d4[base + 4] = lo;

    if (which) {
        // fused block scoring: 4 lanes (jc 0..3) cover one 32-col block segment
        float s = fabsf(a.x) + fabsf(a.y) + fabsf(a.z) + fabsf(a.w) +
                  fabsf(b.x) + fabsf(b.y) + fabsf(b.z) + fabsf(b.w);
        s += __shfl_down_sync(0xFFFFFFFFu, s, 2, 4);
        s += __shfl_down_sync(0xFFFFFFFFu, s, 1, 4);
        if (jc == 0) {
            const int j = (int)(m >> 7);
            atomicAdd(&g_scores[kb * 64 + j], s);
        }
    }
}

// ---------------------------------------------------------------------------
// Kernel B: bitwise radix top-k select (1 CTA, 1024 threads).
// Finds the TOPK-th largest key, marks top-k with jax-style index tiebreak,
// builds per-out-group compacted K-block lists.
// ---------------------------------------------------------------------------
__global__ __launch_bounds__(1024)
void topk_select() {
    __shared__ uint32_t       keys[NBLK];
    __shared__ uint32_t       wsum[32];
    __shared__ uint32_t       s_prefix, s_k;
    __shared__ unsigned char  sel[NBLK];
    const int t    = threadIdx.x;
    const int lane = t & 31;
    const int wid  = t >> 5;

    for (int p = t; p < NBLK; p += 1024) {
        keys[p] = __float_as_uint(g_scores[p]);   // positive floats: uint-orderable
        sel[p]  = 0;
    }
    if (t == 0) { s_prefix = 0; s_k = TOPK; }
    __syncthreads();

    // find threshold key T (value of TOPK-th largest); scores >= 0 so bit31 = 0
    for (int bit = 30; bit >= 0; --bit) {
        uint32_t prefix = s_prefix;
        uint32_t c = 0;
        for (int p = t; p < NBLK; p += 1024) {
            uint32_t key  = keys[p];
            bool cand = ((key ^ prefix) >> (bit + 1)) == 0;
            c += (cand && ((key >> bit) & 1u)) ? 1u : 0u;
        }
        c = __reduce_add_sync(0xFFFFFFFFu, c);
        if (lane == 0) wsum[wid] = c;
        __syncthreads();
        if (t == 0) {
            uint32_t tot = 0;
#pragma unroll
            for (int w = 0; w < 32; ++w) tot += wsum[w];
            if (tot >= s_k) s_prefix |= (1u << bit);
            else            s_k -= tot;
        }
        __syncthreads();
    }

    const uint32_t T     = s_prefix;
    const uint32_t kneed = s_k;   // how many keys == T to take (index order)

    // index-ordered rank among keys == T via block scan (4 consecutive / thread)
    uint32_t e[4], tsum = 0;
#pragma unroll
    for (int j = 0; j < 4; ++j) {
        e[j] = (keys[t * 4 + j] == T) ? 1u : 0u;
        tsum += e[j];
    }
    uint32_t x = tsum;
#pragma unroll
    for (int d = 1; d < 32; d <<= 1) {
        uint32_t y = __shfl_up_sync(0xFFFFFFFFu, x, d);
        if (lane >= d) x += y;
    }
    const uint32_t excl = x - tsum;
    if (lane == 31) wsum[wid] = x;
    __syncthreads();
    if (t == 0) {
        uint32_t run = 0;
#pragma unroll
        for (int w = 0; w < 32; ++w) { uint32_t tmp = wsum[w]; wsum[w] = run; run += tmp; }
    }
    __syncthreads();

    uint32_t r = wsum[wid] + excl;
#pragma unroll
    for (int j = 0; j < 4; ++j) {
        uint32_t key = keys[t * 4 + j];
        if (key > T) sel[t * 4 + j] = 1;
        if (e[j]) { if (r < kneed) sel[t * 4 + j] = 1; r++; }
    }
    __syncthreads();

    if (t < 64) {
        int c = 0;
        for (int i = 0; i < 64; ++i)
            if (sel[i * 64 + t]) g_klist[t * 64 + (c++)] = i;
        g_kcount[t] = c;
    }
}

// ---------------------------------------------------------------------------
// Kernel C: block-sparse GEMM on mma.sync (bf16 hi/lo split, fp32 accum)
// CTA tile 128x128, BK=32 per selected block; 8 warps, warp tile 64x32.
// 3-stage cp.async pipeline, ONE barrier per step (write stage = read stage+2).
// Hi fragments cached across the (hi,hi),(hi,lo),(lo,hi) passes.
// ---------------------------------------------------------------------------
#define AS_OFF      0
#define BS_OFF      16384
#define STAGE_BYTES 32768
#define NSTAGE      3
#define SMEM_TOTAL  (STAGE_BYTES * NSTAGE)

__device__ __forceinline__ void load_tiles(uint32_t stage_base,
                                           const uint4* __restrict__ XC,
                                           const uint4* __restrict__ WC,
                                           int m0, int n0, int kb, int tid) {
    const size_t kb8 = (size_t)kb * 8;
#pragma unroll
    for (int j = 0; j < 4; ++j) {
        int q   = tid + (j << 8);           // 0..1023
        int row = q >> 3;
        int c   = q & 7;
        uint32_t sw = SWZ((uint32_t)(q << 4));
        cp_async16(stage_base + AS_OFF + sw, XC + (size_t)(m0 + row) * 512 + kb8 + c);
        cp_async16(stage_base + BS_OFF + sw, WC + (size_t)(n0 + row) * 512 + kb8 + c);
    }
}

__global__ __launch_bounds__(256, 2)
void mma_kernel(const float* __restrict__ Bias, float* __restrict__ out) {
    extern __shared__ char smem[];
    const uint32_t sb  = smem_u32(smem);
    const int tid  = threadIdx.x;
    const int wid  = tid >> 5;
    const int lane = tid & 31;
    const int ng   = blockIdx.x;
    const int mt   = blockIdx.y;
    const int n0   = ng << 7;
    const int m0   = mt << 7;
    const int cnt  = g_kcount[ng];

    const int wm = wid & 1;        // m half: 0/1 (64 rows each)
    const int wn = wid >> 1;       // n strip: 0..3 (32 cols each)

    if (cnt == 0) {
        const int r  = tid >> 1;
        const int ch = (tid & 1) << 6;
        const float4* bsrc = reinterpret_cast<const float4*>(Bias + n0 + ch);
        float4* drow = reinterpret_cast<float4*>(out + (size_t)(m0 + r) * OUT_F + n0 + ch);
#pragma unroll
        for (int c = 0; c < 16; ++c) drow[c] = bsrc[c];
        return;
    }

    float acc[4][4][4];
#pragma unroll
    for (int i = 0; i < 4; ++i)
#pragma unroll
        for (int j = 0; j < 4; ++j)
#pragma unroll
            for (int k = 0; k < 4; ++k) acc[i][j][k] = 0.f;

    // per-lane ldmatrix addressing components
    const int rowA   = (wm << 6) + (lane & 15);
    const uint32_t aRowOff = (uint32_t)rowA << 7;
    const uint32_t aRot    = (uint32_t)(rowA & 7) << 4;
    const uint32_t aLaneB  = (lane & 16) ? 16u : 0u;

    const int rowB   = (wn << 5) + (lane & 7);
    const uint32_t bRowOff = (uint32_t)rowB << 7;
    const uint32_t bRot    = (uint32_t)(lane & 7) << 4;
    const uint32_t bLaneB  = (lane & 8) ? 16u : 0u;

    const uint4* XC = reinterpret_cast<const uint4*>(g_Xc);
    const uint4* WC = reinterpret_cast<const uint4*>(g_Wc);
    const int* klist = g_klist + (ng << 6);

    // prologue: stages 0 and 1
    load_tiles(sb, XC, WC, m0, n0, klist[0], tid);
    asm volatile("cp.async.commit_group;");
    if (cnt > 1) {
        load_tiles(sb + STAGE_BYTES, XC, WC, m0, n0, klist[1], tid);
        asm volatile("cp.async.commit_group;");
    }

    int s_cur = 0;
    for (int it = 0; it < cnt; ++it) {
        if (it + 1 < cnt) asm volatile("cp.async.wait_group 1;");
        else              asm volatile("cp.async.wait_group 0;");
        __syncthreads();   // load(it) visible to all; all done reading stage (it-1)%3

        if (it + 2 < cnt) {   // issue into stage (it+2)%3 == (it-1)%3 : safe after barrier
            int sl = s_cur + 2; if (sl >= NSTAGE) sl -= NSTAGE;
            load_tiles(sb + sl * STAGE_BYTES, XC, WC, m0, n0, klist[it + 2], tid);
            asm volatile("cp.async.commit_group;");
        }

        const uint32_t aBase = sb + s_cur * STAGE_BYTES + AS_OFF;
        const uint32_t bBase = sb + s_cur * STAGE_BYTES + BS_OFF;

#pragma unroll
        for (int s16 = 0; s16 < 2; ++s16) {
            const uint32_t kOff = (uint32_t)(s16 << 5);
            uint32_t ah[4][4], al[4][4], bh[4][2], bl[4][2];

#pragma unroll
            for (int i = 0; i < 4; ++i)
                ldsm_x4(ah[i], aBase + (i << 11) + aRowOff + ((kOff + aLaneB) ^ aRot));
#pragma unroll
            for (int j = 0; j < 4; ++j)
                ldsm_x2(bh[j], bBase + (j << 10) + bRowOff + ((kOff + bLaneB) ^ bRot));
#pragma unroll
            for (int j = 0; j < 4; ++j)
                ldsm_x2(bl[j], bBase + (j << 10) + bRowOff + ((64u + kOff + bLaneB) ^ bRot));

#pragma unroll
            for (int i = 0; i < 4; ++i)
#pragma unroll
                for (int j = 0; j < 4; ++j)
                    mma16816(acc[i][j], ah[i], bh[j]);   // hi * hi
#pragma unroll
            for (int i = 0; i < 4; ++i)
#pragma unroll
                for (int j = 0; j < 4; ++j)
                    mma16816(acc[i][j], ah[i], bl[j]);   // hi * lo

#pragma unroll
            for (int i = 0; i < 4; ++i)
                ldsm_x4(al[i], aBase + (i << 11) + aRowOff + ((64u + kOff + aLaneB) ^ aRot));
#pragma unroll
            for (int i = 0; i < 4; ++i)
#pragma unroll
                for (int j = 0; j < 4; ++j)
                    mma16816(acc[i][j], al[i], bh[j]);   // lo * hi
        }

        s_cur = (s_cur == NSTAGE - 1) ? 0 : s_cur + 1;
    }

    // Epilogue
    const int cLane = (lane & 3) << 1;
    const int rLane = lane >> 2;
#pragma unroll
    for (int j = 0; j < 4; ++j) {
        const int col = n0 + (wn << 5) + (j << 3) + cLane;
        const float2 bv = *reinterpret_cast<const float2*>(Bias + col);
#pragma unroll
        for (int i = 0; i < 4; ++i) {
            const int row = m0 + (wm << 6) + (i << 4) + rLane;
            float2 o0 = make_float2(acc[i][j][0] + bv.x, acc[i][j][1] + bv.y);
            float2 o1 = make_float2(acc[i][j][2] + bv.x, acc[i][j][3] + bv.y);
            *reinterpret_cast<float2*>(out + (size_t)row * OUT_F + col)       = o0;
            *reinterpret_cast<float2*>(out + (size_t)(row + 8) * OUT_F + col) = o1;
        }
    }
}

// ---------------------------------------------------------------------------
extern "C" void kernel_launch(void* const* d_in, const int* in_sizes, int n_in,
                              void* d_out, int out_size) {
    (void)in_sizes; (void)n_in; (void)out_size;
    const float* X = (const float*)d_in[0];   // (8192, 2048)
    const float* W = (const float*)d_in[1];   // (8192, 2048)
    const float* B = (const float*)d_in[2];   // (8192,)
    float* out = (float*)d_out;               // (8192, 8192)

    cudaFuncSetAttribute(mma_kernel, cudaFuncAttributeMaxDynamicSharedMemorySize,
                         SMEM_TOTAL);

    convert_hilo<<<8192, 256>>>(X, 0);        // also zeroes g_scores
    convert_hilo<<<8192, 256>>>(W, 1);        // fused block scoring
    topk_select<<<1, 1024>>>();
    mma_kernel<<<dim3(64, 64), 256, SMEM_TOTAL>>>(B, out);
}

// round 10
// speedup vs baseline: 2.2414x; 1.0310x over previous
#include <cuda_runtime.h>
#include <cstdint>

#define IN_F   2048
#define OUT_F  8192
#define NROWS  8192
#define NBLK   4096   // 64 in-blocks (32 cols) x 64 out-blocks (128 rows)
#define TOPK   410

// ---------------------------------------------------------------------------
// Scratch (static device memory; no runtime allocation)
// ---------------------------------------------------------------------------
__device__ float g_scores[NBLK];
__device__ int   g_klist[64 * 64];
__device__ int   g_kcount[64];
__device__ int   g_ngord[64];
// Packed bf16 hi|lo: row = 64 blocks x (32 hi + 32 lo) = 4096 ushorts (8192 B)
__device__ __align__(16) unsigned short g_Xc[(size_t)NROWS * 4096];
__device__ __align__(16) unsigned short g_Wc[(size_t)OUT_F * 4096];

// ---------------------------------------------------------------------------
// Helpers
// ---------------------------------------------------------------------------
__device__ __forceinline__ uint32_t smem_u32(const void* p) {
    uint32_t r;
    asm("{ .reg .u64 t; cvta.to.shared.u64 t, %1; cvt.u32.u64 %0, t; }"
        : "=r"(r) : "l"(p));
    return r;
}
#define SWZ(o) ((o) ^ (((o) >> 3) & 0x70))

__device__ __forceinline__ void cp_async16(uint32_t dst, const void* src) {
    asm volatile("cp.async.cg.shared.global [%0], [%1], 16;" :: "r"(dst), "l"(src));
}

__device__ __forceinline__ void ldsm_x4(uint32_t* r, uint32_t addr) {
    asm volatile("ldmatrix.sync.aligned.m8n8.x4.shared.b16 {%0,%1,%2,%3}, [%4];"
                 : "=r"(r[0]), "=r"(r[1]), "=r"(r[2]), "=r"(r[3]) : "r"(addr));
}
__device__ __forceinline__ void mma16816(float* d, const uint32_t* a, const uint32_t* b) {
    asm volatile(
        "mma.sync.aligned.m16n8k16.row.col.f32.bf16.bf16.f32 "
        "{%0,%1,%2,%3}, {%4,%5,%6,%7}, {%8,%9}, {%0,%1,%2,%3};"
        : "+f"(d[0]), "+f"(d[1]), "+f"(d[2]), "+f"(d[3])
        : "r"(a[0]), "r"(a[1]), "r"(a[2]), "r"(a[3]), "r"(b[0]), "r"(b[1]));
}

// ---------------------------------------------------------------------------
// Kernel A: fp32 -> packed bf16 hi|lo, block-interleaved layout.
// One CTA (256 threads) per row. For W (which=1): fused per-block |.| scoring.
// For X (which=0): block 0 also zeroes g_scores for this run.
// ---------------------------------------------------------------------------
__global__ __launch_bounds__(256)
void convert_hilo(const float* __restrict__ src, int which) {
    unsigned short* dst = which ? g_Wc : g_Xc;
    const int tid = threadIdx.x;
    const size_t m = blockIdx.x;           // row
    const int kb = tid >> 2, jc = tid & 3; // k-block, chunk within block

    if (!which && blockIdx.x == 0) {
#pragma unroll
        for (int p = tid; p < NBLK; p += 256) g_scores[p] = 0.f;
    }

    const float4* s4 = reinterpret_cast<const float4*>(src) + (m * 256 + tid) * 2;
    float4 a = s4[0], b = s4[1];

    uint4 hi;
    hi.x = __byte_perm(__float_as_uint(a.x), __float_as_uint(a.y), 0x7632);
    hi.y = __byte_perm(__float_as_uint(a.z), __float_as_uint(a.w), 0x7632);
    hi.z = __byte_perm(__float_as_uint(b.x), __float_as_uint(b.y), 0x7632);
    hi.w = __byte_perm(__float_as_uint(b.z), __float_as_uint(b.w), 0x7632);

    float l0 = a.x - __uint_as_float(__float_as_uint(a.x) & 0xFFFF0000u);
    float l1 = a.y - __uint_as_float(__float_as_uint(a.y) & 0xFFFF0000u);
    float l2 = a.z - __uint_as_float(__float_as_uint(a.z) & 0xFFFF0000u);
    float l3 = a.w - __uint_as_float(__float_as_uint(a.w) & 0xFFFF0000u);
    float l4 = b.x - __uint_as_float(__float_as_uint(b.x) & 0xFFFF0000u);
    float l5 = b.y - __uint_as_float(__float_as_uint(b.y) & 0xFFFF0000u);
    float l6 = b.z - __uint_as_float(__float_as_uint(b.z) & 0xFFFF0000u);
    float l7 = b.w - __uint_as_float(__float_as_uint(b.w) & 0xFFFF0000u);

    uint4 lo;
    asm("cvt.rn.bf16x2.f32 %0, %1, %2;" : "=r"(lo.x) : "f"(l1), "f"(l0));
    asm("cvt.rn.bf16x2.f32 %0, %1, %2;" : "=r"(lo.y) : "f"(l3), "f"(l2));
    asm("cvt.rn.bf16x2.f32 %0, %1, %2;" : "=r"(lo.z) : "f"(l5), "f"(l4));
    asm("cvt.rn.bf16x2.f32 %0, %1, %2;" : "=r"(lo.w) : "f"(l7), "f"(l6));

    uint4* d4 = reinterpret_cast<uint4*>(dst);
    size_t base = m * 512 + (size_t)kb * 8 + jc;
    d4[base]     = hi;
    d4[base + 4] = lo;

    if (which) {
        float s = fabsf(a.x) + fabsf(a.y) + fabsf(a.z) + fabsf(a.w) +
                  fabsf(b.x) + fabsf(b.y) + fabsf(b.z) + fabsf(b.w);
        s += __shfl_down_sync(0xFFFFFFFFu, s, 2, 4);
        s += __shfl_down_sync(0xFFFFFFFFu, s, 1, 4);
        if (jc == 0) {
            const int j = (int)(m >> 7);
            atomicAdd(&g_scores[kb * 64 + j], s);
        }
    }
}

// ---------------------------------------------------------------------------
// Kernel B: bitwise radix top-k select (1 CTA, 1024 threads).
// Also emits g_ngord: n-groups sorted by descending k-block count.
// ---------------------------------------------------------------------------
__global__ __launch_bounds__(1024)
void topk_select() {
    __shared__ uint32_t       keys[NBLK];
    __shared__ uint32_t       wsum[32];
    __shared__ uint32_t       s_prefix, s_k;
    __shared__ unsigned char  sel[NBLK];
    const int t    = threadIdx.x;
    const int lane = t & 31;
    const int wid  = t >> 5;

    for (int p = t; p < NBLK; p += 1024) {
        keys[p] = __float_as_uint(g_scores[p]);   // positive floats: uint-orderable
        sel[p]  = 0;
    }
    if (t == 0) { s_prefix = 0; s_k = TOPK; }
    __syncthreads();

    for (int bit = 30; bit >= 0; --bit) {
        uint32_t prefix = s_prefix;
        uint32_t c = 0;
        for (int p = t; p < NBLK; p += 1024) {
            uint32_t key  = keys[p];
            bool cand = ((key ^ prefix) >> (bit + 1)) == 0;
            c += (cand && ((key >> bit) & 1u)) ? 1u : 0u;
        }
        c = __reduce_add_sync(0xFFFFFFFFu, c);
        if (lane == 0) wsum[wid] = c;
        __syncthreads();
        if (t == 0) {
            uint32_t tot = 0;
#pragma unroll
            for (int w = 0; w < 32; ++w) tot += wsum[w];
            if (tot >= s_k) s_prefix |= (1u << bit);
            else            s_k -= tot;
        }
        __syncthreads();
    }

    const uint32_t T     = s_prefix;
    const uint32_t kneed = s_k;

    uint32_t e[4], tsum = 0;
#pragma unroll
    for (int j = 0; j < 4; ++j) {
        e[j] = (keys[t * 4 + j] == T) ? 1u : 0u;
        tsum += e[j];
    }
    uint32_t x = tsum;
#pragma unroll
    for (int d = 1; d < 32; d <<= 1) {
        uint32_t y = __shfl_up_sync(0xFFFFFFFFu, x, d);
        if (lane >= d) x += y;
    }
    const uint32_t excl = x - tsum;
    if (lane == 31) wsum[wid] = x;
    __syncthreads();
    if (t == 0) {
        uint32_t run = 0;
#pragma unroll
        for (int w = 0; w < 32; ++w) { uint32_t tmp = wsum[w]; wsum[w] = run; run += tmp; }
    }
    __syncthreads();

    uint32_t r = wsum[wid] + excl;
#pragma unroll
    for (int j = 0; j < 4; ++j) {
        uint32_t key = keys[t * 4 + j];
        if (key > T) sel[t * 4 + j] = 1;
        if (e[j]) { if (r < kneed) sel[t * 4 + j] = 1; r++; }
    }
    __syncthreads();

    if (t < 64) {
        int c = 0;
        for (int i = 0; i < 64; ++i)
            if (sel[i * 64 + t]) g_klist[t * 64 + (c++)] = i;
        g_kcount[t] = c;
    }
    __syncthreads();
    if (t < 64) {
        const int myc = g_kcount[t];
        int rank = 0;
        for (int i = 0; i < 64; ++i) {
            const int ci = g_kcount[i];
            rank += (ci > myc) || (ci == myc && i < t);
        }
        g_ngord[rank] = t;   // heavy n-groups first
    }
}

// ---------------------------------------------------------------------------
// Kernel C: block-sparse GEMM on mma.sync (bf16 hi/lo split, fp32 accum)
// CTA tile 128x128, 4 warps, warp tile 64x64 (4 m-frags x 8 n-frags).
// 3-stage cp.async pipeline, one barrier per step. B loaded via ldsm_x4
// (2 n8-frags per instruction). MMA:LDSM = 6:1.
// ---------------------------------------------------------------------------
#define AS_OFF      0
#define BS_OFF      16384
#define STAGE_BYTES 32768
#define NSTAGE      3
#define SMEM_TOTAL  (STAGE_BYTES * NSTAGE)

__device__ __forceinline__ void load_tiles(uint32_t stage_base,
                                           const uint4* __restrict__ XC,
                                           const uint4* __restrict__ WC,
                                           int m0, int n0, int kb, int tid) {
    const size_t kb8 = (size_t)kb * 8;
#pragma unroll
    for (int j = 0; j < 8; ++j) {
        int q   = tid + (j << 7);           // 0..1023 over A region
        int row = q >> 3;
        int c   = q & 7;
        uint32_t sw = SWZ((uint32_t)(q << 4));
        cp_async16(stage_base + AS_OFF + sw, XC + (size_t)(m0 + row) * 512 + kb8 + c);
        cp_async16(stage_base + BS_OFF + sw, WC + (size_t)(n0 + row) * 512 + kb8 + c);
    }
}

__global__ __launch_bounds__(128, 2)
void mma_kernel(const float* __restrict__ Bias, float* __restrict__ out) {
    extern __shared__ char smem[];
    const uint32_t sb  = smem_u32(smem);
    const int tid  = threadIdx.x;
    const int wid  = tid >> 5;
    const int lane = tid & 31;
    const int ng   = g_ngord[blockIdx.x];
    const int mt   = blockIdx.y;
    const int n0   = ng << 7;
    const int m0   = mt << 7;
    const int cnt  = g_kcount[ng];

    const int wm = wid & 1;        // m half (64 rows)
    const int wn = wid >> 1;       // n half (64 cols)

    if (cnt == 0) {
        // bias-only tile: thread = row
        const float4* bsrc = reinterpret_cast<const float4*>(Bias + n0);
        float4* drow = reinterpret_cast<float4*>(out + (size_t)(m0 + tid) * OUT_F + n0);
#pragma unroll
        for (int c = 0; c < 32; ++c) drow[c] = bsrc[c];
        return;
    }

    float acc[4][8][4];
#pragma unroll
    for (int i = 0; i < 4; ++i)
#pragma unroll
        for (int j = 0; j < 8; ++j)
#pragma unroll
            for (int k = 0; k < 4; ++k) acc[i][j][k] = 0.f;

    // A ldmatrix addressing
    const int rowA         = (wm << 6) + (lane & 15);
    const uint32_t aRowOff = (uint32_t)rowA << 7;
    const uint32_t aRot    = (uint32_t)(rowA & 7) << 4;
    const uint32_t aLaneB  = (lane & 16) ? 16u : 0u;

    // B ldmatrix (x4 -> 2 n8-frags) addressing:
    // lanes 0-7: n rows +0, k +0 | 8-15: n rows +0, k +16 | 16-23: +8,+0 | 24-31: +8,+16
    const int rowB         = (wn << 6) + ((lane >> 4) << 3) + (lane & 7);
    const uint32_t bRowOff = (uint32_t)rowB << 7;
    const uint32_t bRot    = (uint32_t)(lane & 7) << 4;
    const uint32_t kSel    = (uint32_t)((lane >> 3) & 1) << 4;

    const uint4* XC = reinterpret_cast<const uint4*>(g_Xc);
    const uint4* WC = reinterpret_cast<const uint4*>(g_Wc);
    const int* klist = g_klist + (ng << 6);

    // prologue: stages 0 and 1
    load_tiles(sb, XC, WC, m0, n0, klist[0], tid);
    asm volatile("cp.async.commit_group;");
    if (cnt > 1) {
        load_tiles(sb + STAGE_BYTES, XC, WC, m0, n0, klist[1], tid);
        asm volatile("cp.async.commit_group;");
    }

    int s_cur = 0;
    for (int it = 0; it < cnt; ++it) {
        if (it + 1 < cnt) asm volatile("cp.async.wait_group 1;");
        else              asm volatile("cp.async.wait_group 0;");
        __syncthreads();

        if (it + 2 < cnt) {
            int sl = s_cur + 2; if (sl >= NSTAGE) sl -= NSTAGE;
            load_tiles(sb + sl * STAGE_BYTES, XC, WC, m0, n0, klist[it + 2], tid);
            asm volatile("cp.async.commit_group;");
        }

        const uint32_t aBase = sb + s_cur * STAGE_BYTES + AS_OFF;
        const uint32_t bBase = sb + s_cur * STAGE_BYTES + BS_OFF;

#pragma unroll
        for (int s16 = 0; s16 < 2; ++s16) {
            const uint32_t kOff = (uint32_t)(s16 << 5);
            uint32_t ah[4][4], al[4][4], bh[16], bl[16];

#pragma unroll
            for (int i = 0; i < 4; ++i)
                ldsm_x4(ah[i], aBase + (i << 11) + aRowOff + ((kOff + aLaneB) ^ aRot));
#pragma unroll
            for (int j2 = 0; j2 < 4; ++j2)
                ldsm_x4(bh + j2 * 4, bBase + (j2 << 11) + bRowOff + ((kOff + kSel) ^ bRot));

#pragma unroll
            for (int i = 0; i < 4; ++i)
#pragma unroll
                for (int j = 0; j < 8; ++j)
                    mma16816(acc[i][j], ah[i], bh + j * 2);     // hi * hi

#pragma unroll
            for (int i = 0; i < 4; ++i)
                ldsm_x4(al[i], aBase + (i << 11) + aRowOff + ((64u + kOff + aLaneB) ^ aRot));
#pragma unroll
            for (int i = 0; i < 4; ++i)
#pragma unroll
                for (int j = 0; j < 8; ++j)
                    mma16816(acc[i][j], al[i], bh + j * 2);     // lo * hi

#pragma unroll
            for (int j2 = 0; j2 < 4; ++j2)
                ldsm_x4(bl + j2 * 4, bBase + (j2 << 11) + bRowOff + ((64u + kOff + kSel) ^ bRot));
#pragma unroll
            for (int i = 0; i < 4; ++i)
#pragma unroll
                for (int j = 0; j < 8; ++j)
                    mma16816(acc[i][j], ah[i], bl + j * 2);     // hi * lo
        }

        s_cur = (s_cur == NSTAGE - 1) ? 0 : s_cur + 1;
    }

    // Epilogue
    const int cLane = (lane & 3) << 1;
    const int rLane = lane >> 2;
#pragma unroll
    for (int j = 0; j < 8; ++j) {
        const int col = n0 + (wn << 6) + (j << 3) + cLane;
        const float2 bv = *reinterpret_cast<const float2*>(Bias + col);
#pragma unroll
        for (int i = 0; i < 4; ++i) {
            const int row = m0 + (wm << 6) + (i << 4) + rLane;
            float2 o0 = make_float2(acc[i][j][0] + bv.x, acc[i][j][1] + bv.y);
            float2 o1 = make_float2(acc[i][j][2] + bv.x, acc[i][j][3] + bv.y);
            *reinterpret_cast<float2*>(out + (size_t)row * OUT_F + col)       = o0;
            *reinterpret_cast<float2*>(out + (size_t)(row + 8) * OUT_F + col) = o1;
        }
    }
}

// ---------------------------------------------------------------------------
extern "C" void kernel_launch(void* const* d_in, const int* in_sizes, int n_in,
                              void* d_out, int out_size) {
    (void)in_sizes; (void)n_in; (void)out_size;
    const float* X = (const float*)d_in[0];   // (8192, 2048)
    const float* W = (const float*)d_in[1];   // (8192, 2048)
    const float* B = (const float*)d_in[2];   // (8192,)
    float* out = (float*)d_out;               // (8192, 8192)

    cudaFuncSetAttribute(mma_kernel, cudaFuncAttributeMaxDynamicSharedMemorySize,
                         SMEM_TOTAL);

    convert_hilo<<<8192, 256>>>(X, 0);        // also zeroes g_scores
    convert_hilo<<<8192, 256>>>(W, 1);        // fused block scoring
    topk_select<<<1, 1024>>>();
    mma_kernel<<<dim3(64, 64), 128, SMEM_TOTAL>>>(B, out);
}

// round 11
// speedup vs baseline: 3.5842x; 1.5991x over previous
#include <cuda_runtime.h>
#include <cuda_fp16.h>
#include <cstdint>

#define IN_F   2048
#define OUT_F  8192
#define NROWS  8192
#define NBLK   4096   // 64 in-blocks (32 cols) x 64 out-blocks (128 rows)
#define TOPK   410

// ---------------------------------------------------------------------------
// Scratch (static device memory; no runtime allocation)
// ---------------------------------------------------------------------------
__device__ float g_scores[NBLK];
__device__ int   g_klist[64 * 64];
__device__ int   g_kcount[64];
__device__ int   g_ngord[64];
// fp16 copies, natural row-major layout (row = 2048 fp16 = 4KB)
__device__ __align__(16) unsigned short g_Xh[(size_t)NROWS * IN_F];
__device__ __align__(16) unsigned short g_Wh[(size_t)OUT_F * IN_F];

// ---------------------------------------------------------------------------
// Helpers
// ---------------------------------------------------------------------------
__device__ __forceinline__ uint32_t smem_u32(const void* p) {
    uint32_t r;
    asm("{ .reg .u64 t; cvta.to.shared.u64 t, %1; cvt.u32.u64 %0, t; }"
        : "=r"(r) : "l"(p));
    return r;
}

__device__ __forceinline__ void cp_async16(uint32_t dst, const void* src) {
    asm volatile("cp.async.cg.shared.global [%0], [%1], 16;" :: "r"(dst), "l"(src));
}

__device__ __forceinline__ void ldsm_x4(uint32_t* r, uint32_t addr) {
    asm volatile("ldmatrix.sync.aligned.m8n8.x4.shared.b16 {%0,%1,%2,%3}, [%4];"
                 : "=r"(r[0]), "=r"(r[1]), "=r"(r[2]), "=r"(r[3]) : "r"(addr));
}
__device__ __forceinline__ void mma16816(float* d, const uint32_t* a, const uint32_t* b) {
    asm volatile(
        "mma.sync.aligned.m16n8k16.row.col.f32.f16.f16.f32 "
        "{%0,%1,%2,%3}, {%4,%5,%6,%7}, {%8,%9}, {%0,%1,%2,%3};"
        : "+f"(d[0]), "+f"(d[1]), "+f"(d[2]), "+f"(d[3])
        : "r"(a[0]), "r"(a[1]), "r"(a[2]), "r"(a[3]), "r"(b[0]), "r"(b[1]));
}

// Panel layout in SMEM: 128 rows x 64B (32 fp16), two rows per 128B line,
// 16B chunk (row, c) stored at line=row>>1, slot=((row&1)*4+c)^(line&7):
//   off(row, c) = (row>>1)*128 + ((((row&1)<<2) + (c)) ^ ((row>>1)&7))*16
__device__ __forceinline__ uint32_t panel_off(int row, int c) {
    return (uint32_t)((row >> 1) * 128 +
                      (((((row & 1) << 2) + c) ^ ((row >> 1) & 7)) << 4));
}

// ---------------------------------------------------------------------------
// Kernel A: fp32 -> fp16 row copy. For W (which=1): fused per-block |.| score.
// For X (which=0): block 0 also zeroes g_scores for this run.
// ---------------------------------------------------------------------------
__global__ __launch_bounds__(256)
void convert_f16(const float* __restrict__ src, int which) {
    unsigned short* dst = which ? g_Wh : g_Xh;
    const int tid = threadIdx.x;
    const size_t m = blockIdx.x;

    if (!which && blockIdx.x == 0) {
#pragma unroll
        for (int p = tid; p < NBLK; p += 256) g_scores[p] = 0.f;
    }

    const float4* s4 = reinterpret_cast<const float4*>(src) + m * 512 + tid * 2;
    float4 a = s4[0], b = s4[1];

    __half2 h0 = __floats2half2_rn(a.x, a.y);
    __half2 h1 = __floats2half2_rn(a.z, a.w);
    __half2 h2 = __floats2half2_rn(b.x, b.y);
    __half2 h3 = __floats2half2_rn(b.z, b.w);
    uint4 o;
    o.x = *reinterpret_cast<uint32_t*>(&h0);
    o.y = *reinterpret_cast<uint32_t*>(&h1);
    o.z = *reinterpret_cast<uint32_t*>(&h2);
    o.w = *reinterpret_cast<uint32_t*>(&h3);
    reinterpret_cast<uint4*>(dst)[m * 256 + tid] = o;

    if (which) {
        // 4 lanes (jc = tid&3) cover one 32-col k-block segment of this row
        float s = fabsf(a.x) + fabsf(a.y) + fabsf(a.z) + fabsf(a.w) +
                  fabsf(b.x) + fabsf(b.y) + fabsf(b.z) + fabsf(b.w);
        s += __shfl_down_sync(0xFFFFFFFFu, s, 2, 4);
        s += __shfl_down_sync(0xFFFFFFFFu, s, 1, 4);
        if ((tid & 3) == 0) {
            const int kb = tid >> 2;
            const int j  = (int)(m >> 7);
            atomicAdd(&g_scores[kb * 64 + j], s);
        }
    }
}

// ---------------------------------------------------------------------------
// Kernel B: bitwise radix top-k select (1 CTA, 1024 threads).
// Emits g_klist/g_kcount and g_ngord (n-groups by descending count).
// ---------------------------------------------------------------------------
__global__ __launch_bounds__(1024)
void topk_select() {
    __shared__ uint32_t       keys[NBLK];
    __shared__ uint32_t       wsum[32];
    __shared__ uint32_t       s_prefix, s_k;
    __shared__ unsigned char  sel[NBLK];
    const int t    = threadIdx.x;
    const int lane = t & 31;
    const int wid  = t >> 5;

    for (int p = t; p < NBLK; p += 1024) {
        keys[p] = __float_as_uint(g_scores[p]);   // positive floats: uint-orderable
        sel[p]  = 0;
    }
    if (t == 0) { s_prefix = 0; s_k = TOPK; }
    __syncthreads();

    for (int bit = 30; bit >= 0; --bit) {
        uint32_t prefix = s_prefix;
        uint32_t c = 0;
        for (int p = t; p < NBLK; p += 1024) {
            uint32_t key  = keys[p];
            bool cand = ((key ^ prefix) >> (bit + 1)) == 0;
            c += (cand && ((key >> bit) & 1u)) ? 1u : 0u;
        }
        c = __reduce_add_sync(0xFFFFFFFFu, c);
        if (lane == 0) wsum[wid] = c;
        __syncthreads();
        if (t == 0) {
            uint32_t tot = 0;
#pragma unroll
            for (int w = 0; w < 32; ++w) tot += wsum[w];
            if (tot >= s_k) s_prefix |= (1u << bit);
            else            s_k -= tot;
        }
        __syncthreads();
    }

    const uint32_t T     = s_prefix;
    const uint32_t kneed = s_k;

    uint32_t e[4], tsum = 0;
#pragma unroll
    for (int j = 0; j < 4; ++j) {
        e[j] = (keys[t * 4 + j] == T) ? 1u : 0u;
        tsum += e[j];
    }
    uint32_t x = tsum;
#pragma unroll
    for (int d = 1; d < 32; d <<= 1) {
        uint32_t y = __shfl_up_sync(0xFFFFFFFFu, x, d);
        if (lane >= d) x += y;
    }
    const uint32_t excl = x - tsum;
    if (lane == 31) wsum[wid] = x;
    __syncthreads();
    if (t == 0) {
        uint32_t run = 0;
#pragma unroll
        for (int w = 0; w < 32; ++w) { uint32_t tmp = wsum[w]; wsum[w] = run; run += tmp; }
    }
    __syncthreads();

    uint32_t r = wsum[wid] + excl;
#pragma unroll
    for (int j = 0; j < 4; ++j) {
        uint32_t key = keys[t * 4 + j];
        if (key > T) sel[t * 4 + j] = 1;
        if (e[j]) { if (r < kneed) sel[t * 4 + j] = 1; r++; }
    }
    __syncthreads();

    if (t < 64) {
        int c = 0;
        for (int i = 0; i < 64; ++i)
            if (sel[i * 64 + t]) g_klist[t * 64 + (c++)] = i;
        g_kcount[t] = c;
    }
    __syncthreads();
    if (t < 64) {
        const int myc = g_kcount[t];
        int rank = 0;
        for (int i = 0; i < 64; ++i) {
            const int ci = g_kcount[i];
            rank += (ci > myc) || (ci == myc && i < t);
        }
        g_ngord[rank] = t;   // heavy n-groups first
    }
}

// ---------------------------------------------------------------------------
// Kernel C: block-sparse GEMM, single-pass fp16 mma.sync, fp32 accum.
// CTA tile 128x128, 4 warps, warp tile 64x64. 4-stage cp.async pipeline,
// one barrier per step. Panels are 128 rows x 64B with line-swizzle.
// ---------------------------------------------------------------------------
#define AS_OFF      0
#define BS_OFF      8192
#define STAGE_BYTES 16384
#define NSTAGE      4
#define SMEM_TOTAL  (STAGE_BYTES * NSTAGE)

__device__ __forceinline__ void load_tiles(uint32_t stage_base,
                                           const uint4* __restrict__ XH,
                                           const uint4* __restrict__ WH,
                                           int m0, int n0, int kb, int tid) {
    const int kb4 = kb * 4;
#pragma unroll
    for (int j = 0; j < 4; ++j) {
        int q   = tid + (j << 7);           // 0..511 chunks per panel
        int row = q >> 2;
        int c   = q & 3;
        uint32_t off = panel_off(row, c);
        cp_async16(stage_base + AS_OFF + off, XH + (size_t)(m0 + row) * 256 + kb4 + c);
        cp_async16(stage_base + BS_OFF + off, WH + (size_t)(n0 + row) * 256 + kb4 + c);
    }
}

__global__ __launch_bounds__(128, 2)
void mma_kernel(const float* __restrict__ Bias, float* __restrict__ out) {
    extern __shared__ char smem[];
    const uint32_t sb  = smem_u32(smem);
    const int tid  = threadIdx.x;
    const int wid  = tid >> 5;
    const int lane = tid & 31;
    const int ng   = g_ngord[blockIdx.x];
    const int mt   = blockIdx.y;
    const int n0   = ng << 7;
    const int m0   = mt << 7;
    const int cnt  = g_kcount[ng];

    const int wm = wid & 1;        // m half (64 rows)
    const int wn = wid >> 1;       // n half (64 cols)

    if (cnt == 0) {
        const float4* bsrc = reinterpret_cast<const float4*>(Bias + n0);
        float4* drow = reinterpret_cast<float4*>(out + (size_t)(m0 + tid) * OUT_F + n0);
#pragma unroll
        for (int c = 0; c < 32; ++c) drow[c] = bsrc[c];
        return;
    }

    float acc[4][8][4];
#pragma unroll
    for (int i = 0; i < 4; ++i)
#pragma unroll
        for (int j = 0; j < 8; ++j)
#pragma unroll
            for (int k = 0; k < 4; ++k) acc[i][j][k] = 0.f;

    // Precomputed per-lane fragment offsets within a panel.
    // A (x4): lanes 0-15 -> rows m+0..15, chunk +0; lanes 16-31 -> same rows, chunk +1
    uint32_t aOff[4][2];
#pragma unroll
    for (int i = 0; i < 4; ++i) {
        const int rowA = (wm << 6) + (i << 4) + (lane & 15);
#pragma unroll
        for (int s16 = 0; s16 < 2; ++s16)
            aOff[i][s16] = panel_off(rowA, (s16 << 1) + (lane >> 4));
    }
    // B (x4 -> 2 n8 frags): lanes 0-7 n+0..7 k+0 | 8-15 n+0..7 k+8 | 16-23 n+8..15 k+0 | 24-31 n+8..15 k+8
    uint32_t bOff[4][2];
#pragma unroll
    for (int j2 = 0; j2 < 4; ++j2) {
        const int rowB = (wn << 6) + (j2 << 4) + (((lane >> 4) & 1) << 3) + (lane & 7);
#pragma unroll
        for (int s16 = 0; s16 < 2; ++s16)
            bOff[j2][s16] = panel_off(rowB, (s16 << 1) + ((lane >> 3) & 1));
    }

    const uint4* XH = reinterpret_cast<const uint4*>(g_Xh);
    const uint4* WH = reinterpret_cast<const uint4*>(g_Wh);
    const int* klist = g_klist + (ng << 6);

    // prologue: stages 0..2
#pragma unroll
    for (int p = 0; p < NSTAGE - 1; ++p) {
        if (p < cnt) {
            load_tiles(sb + p * STAGE_BYTES, XH, WH, m0, n0, klist[p], tid);
            asm volatile("cp.async.commit_group;");
        }
    }

    int s_cur = 0;
    for (int it = 0; it < cnt; ++it) {
        if (it + 3 <= cnt - 1 + 1 && it + 3 <= cnt) { /* committed it+3 groups so far? */ }
        if (it + 3 <= cnt)      asm volatile("cp.async.wait_group 2;");
        else if (it + 2 == cnt) asm volatile("cp.async.wait_group 1;");
        else                    asm volatile("cp.async.wait_group 0;");
        __syncthreads();

        if (it + 3 < cnt) {
            int sl = s_cur + 3; if (sl >= NSTAGE) sl -= NSTAGE;
            load_tiles(sb + sl * STAGE_BYTES, XH, WH, m0, n0, klist[it + 3], tid);
            asm volatile("cp.async.commit_group;");
        }

        const uint32_t aBase = sb + s_cur * STAGE_BYTES + AS_OFF;
        const uint32_t bBase = sb + s_cur * STAGE_BYTES + BS_OFF;

#pragma unroll
        for (int s16 = 0; s16 < 2; ++s16) {
            uint32_t af[4][4], bf[16];
#pragma unroll
            for (int i = 0; i < 4; ++i)
                ldsm_x4(af[i], aBase + aOff[i][s16]);
#pragma unroll
            for (int j2 = 0; j2 < 4; ++j2)
                ldsm_x4(bf + j2 * 4, bBase + bOff[j2][s16]);

#pragma unroll
            for (int i = 0; i < 4; ++i)
#pragma unroll
                for (int j = 0; j < 8; ++j)
                    mma16816(acc[i][j], af[i], bf + j * 2);
        }

        s_cur = (s_cur == NSTAGE - 1) ? 0 : s_cur + 1;
    }

    // Epilogue
    const int cLane = (lane & 3) << 1;
    const int rLane = lane >> 2;
#pragma unroll
    for (int j = 0; j < 8; ++j) {
        const int col = n0 + (wn << 6) + (j << 3) + cLane;
        const float2 bv = *reinterpret_cast<const float2*>(Bias + col);
#pragma unroll
        for (int i = 0; i < 4; ++i) {
            const int row = m0 + (wm << 6) + (i << 4) + rLane;
            float2 o0 = make_float2(acc[i][j][0] + bv.x, acc[i][j][1] + bv.y);
            float2 o1 = make_float2(acc[i][j][2] + bv.x, acc[i][j][3] + bv.y);
            *reinterpret_cast<float2*>(out + (size_t)row * OUT_F + col)       = o0;
            *reinterpret_cast<float2*>(out + (size_t)(row + 8) * OUT_F + col) = o1;
        }
    }
}

// ---------------------------------------------------------------------------
extern "C" void kernel_launch(void* const* d_in, const int* in_sizes, int n_in,
                              void* d_out, int out_size) {
    (void)in_sizes; (void)n_in; (void)out_size;
    const float* X = (const float*)d_in[0];   // (8192, 2048)
    const float* W = (const float*)d_in[1];   // (8192, 2048)
    const float* B = (const float*)d_in[2];   // (8192,)
    float* out = (float*)d_out;               // (8192, 8192)

    cudaFuncSetAttribute(mma_kernel, cudaFuncAttributeMaxDynamicSharedMemorySize,
                         SMEM_TOTAL);

    convert_f16<<<8192, 256>>>(X, 0);         // also zeroes g_scores
    convert_f16<<<8192, 256>>>(W, 1);         // fused block scoring
    topk_select<<<1, 1024>>>();
    mma_kernel<<<dim3(64, 64), 128, SMEM_TOTAL>>>(B, out);
}